// round 1
// baseline (speedup 1.0000x reference)
#include <cuda_runtime.h>
#include <math.h>

// Shapes (fixed by the problem): hidden_states (8, 4096, 1024) f32,
// W (1024, 1024) f32, b (1024) f32, alpha (1) f32.  Output (8, 1, 1024) f32.
#define BATCH 8
#define SEQ   4096
#define HID   1024
#define WORDS (HID / 32)   // 32 packed 32-bit sign words per row

// Scratch (allocation-free requirement -> __device__ globals).
// All of these are fully rewritten on every kernel_launch call.
__device__ unsigned g_xneg[BATCH][WORDS];   // sign bit of x_first (x < 0)
__device__ unsigned g_xnz [BATCH][WORDS];   // nonzero mask of x_first
__device__ int      g_dot [HID * BATCH];    // [o][b] integer sign-dot
__device__ float    g_wpart[HID];           // per-row sum of |W|

// ---------------------------------------------------------------------------
// Kernel 0: pack sign / nonzero bits of the 8 first-token rows (8 x 1024 f32).
// 1 block, 256 threads = 8 warps; warp w handles batch b = w.
// ---------------------------------------------------------------------------
__global__ void pack_x_kernel(const float* __restrict__ x)
{
    const int warp = threadIdx.x >> 5;   // batch index
    const int lane = threadIdx.x & 31;
    const float* xb = x + (size_t)warp * SEQ * HID;   // first token of batch

    #pragma unroll
    for (int j = 0; j < WORDS; ++j) {
        float v = xb[j * 32 + lane];
        unsigned neg = __ballot_sync(0xffffffffu, v < 0.0f);
        unsigned nz  = __ballot_sync(0xffffffffu, v != 0.0f);
        if (lane == 0) {
            g_xneg[warp][j] = neg;
            g_xnz [warp][j] = nz;
        }
    }
}

// ---------------------------------------------------------------------------
// Kernel 1: one block per output row o (row of W).
// 256 threads = 8 warps; warp w covers h in [w*128, w*128+128) as 4 ballots.
// Produces: g_dot[o*8 + b] (exact integer +-1 dot) and g_wpart[o] = sum |W[o,:]|.
// ---------------------------------------------------------------------------
__global__ void row_kernel(const float* __restrict__ Wm)
{
    const int o    = blockIdx.x;
    const int warp = threadIdx.x >> 5;
    const int lane = threadIdx.x & 31;
    const float* wr = Wm + (size_t)o * HID;

    int   acc[BATCH];
    #pragma unroll
    for (int b = 0; b < BATCH; ++b) acc[b] = 0;
    float asum = 0.0f;

    #pragma unroll
    for (int j = 0; j < 4; ++j) {
        const int word = warp * 4 + j;
        float wv = wr[word * 32 + lane];          // coalesced 128B per warp
        asum += fabsf(wv);
        unsigned wneg = __ballot_sync(0xffffffffu, wv < 0.0f);
        unsigned wnz  = __ballot_sync(0xffffffffu, wv != 0.0f);
        #pragma unroll
        for (int b = 0; b < BATCH; ++b) {
            unsigned valid = g_xnz[b][word] & wnz;
            unsigned diff  = (g_xneg[b][word] ^ wneg) & valid;
            acc[b] += __popc(valid) - 2 * __popc(diff);   // uniform across warp
        }
    }

    // |W| warp reduction (acc[] is already warp-uniform; no reduce needed)
    #pragma unroll
    for (int off = 16; off > 0; off >>= 1)
        asum += __shfl_xor_sync(0xffffffffu, asum, off);

    __shared__ float s_asum[8];
    __shared__ int   s_acc[8][BATCH];
    if (lane == 0) {
        s_asum[warp] = asum;
        #pragma unroll
        for (int b = 0; b < BATCH; ++b) s_acc[warp][b] = acc[b];
    }
    __syncthreads();

    if (threadIdx.x < BATCH) {
        const int b = threadIdx.x;
        int tot = 0;
        #pragma unroll
        for (int w2 = 0; w2 < 8; ++w2) tot += s_acc[w2][b];
        g_dot[o * BATCH + b] = tot;
    }
    if (threadIdx.x == BATCH) {   // one thread sums the 8 warp partials
        float t = 0.0f;
        #pragma unroll
        for (int w2 = 0; w2 < 8; ++w2) t += s_asum[w2];
        g_wpart[o] = t;
    }
}

// ---------------------------------------------------------------------------
// Kernel 2: reduce sum|W| -> w_scale, then out[b][o] = tanh(a*ws*dot + bias[o]).
// 1 block, 1024 threads (thread t = output column o).
// ---------------------------------------------------------------------------
__global__ void epilogue_kernel(const float* __restrict__ bias,
                                const float* __restrict__ alpha,
                                float* __restrict__ out)
{
    __shared__ float red[HID];
    const int t = threadIdx.x;
    red[t] = g_wpart[t];
    __syncthreads();
    #pragma unroll
    for (int s = 512; s > 0; s >>= 1) {
        if (t < s) red[t] += red[t + s];
        __syncthreads();
    }
    const float wscale = red[0] * (1.0f / ((float)HID * (float)HID));
    const float a      = fmaxf(alpha[0], 1e-5f);
    const float scale  = a * wscale;
    const float bo     = bias[t];

    #pragma unroll
    for (int b = 0; b < BATCH; ++b) {
        out[b * HID + t] = tanhf(scale * (float)g_dot[t * BATCH + b] + bo);
    }
}

// ---------------------------------------------------------------------------
extern "C" void kernel_launch(void* const* d_in, const int* in_sizes, int n_in,
                              void* d_out, int out_size)
{
    const float* x     = (const float*)d_in[0];   // hidden_states
    const float* Wm    = (const float*)d_in[1];   // W
    const float* bias  = (const float*)d_in[2];   // b
    const float* alpha = (const float*)d_in[3];   // alpha
    float* out = (float*)d_out;

    pack_x_kernel <<<1, 256>>>(x);
    row_kernel    <<<HID, 256>>>(Wm);
    epilogue_kernel<<<1, 1024>>>(bias, alpha, out);
}

// round 4
// speedup vs baseline: 1.2579x; 1.2579x over previous
#include <cuda_runtime.h>
#include <math.h>

// Shapes fixed by the problem:
//   hidden_states (8, 4096, 1024) f32, W (1024,1024) f32, b (1024) f32,
//   alpha (1) f32.  Output (8, 1, 1024) f32.
#define BATCH 8
#define SEQ   4096
#define HID   1024
#define CHUNKS 8                  // 8 chunks of 128 elements per row
#define WORDS  (CHUNKS * 4)       // 32 sign-words per row (word j=c*4+k)
#define ROWS_PER_BLOCK 8          // one warp per W row
#define NBLOCKS (HID / ROWS_PER_BLOCK)   // 128
#define NTHREADS 256

// Bit layout (identical for x and W, which is all correctness needs):
//   word (c*4+k), bit `lane`  <->  element h = c*128 + 4*lane + k

// Scratch (__device__ globals; allocation-free rule). Rewritten every call.
__device__ int      g_dot[HID * BATCH];    // [o][b] exact integer sign-dot
__device__ float    g_wpart[HID];          // per-row sum |W[o,:]|
__device__ unsigned g_ticket = 0;          // last-block-done counter (self-resetting)

__global__ void __launch_bounds__(NTHREADS, 2)
fused_pooler_kernel(const float* __restrict__ x,
                    const float* __restrict__ Wm,
                    const float* __restrict__ bias,
                    const float* __restrict__ alpha,
                    float* __restrict__ out)
{
    const int tid  = threadIdx.x;
    const int warp = tid >> 5;
    const int lane = tid & 31;

    // ---- Phase A: pack sign/nonzero bits of the 8 first tokens into smem ----
    __shared__ unsigned s_xneg[WORDS][BATCH];
    __shared__ unsigned s_xnz [WORDS][BATCH];

    {
        // warp w packs batch w (8 warps == 8 batches); float4 per lane
        const float4* xb = (const float4*)(x + (size_t)warp * SEQ * HID);
        #pragma unroll
        for (int c = 0; c < CHUNKS; ++c) {
            float4 v = __ldg(xb + c * 32 + lane);
            const float e[4] = {v.x, v.y, v.z, v.w};
            #pragma unroll
            for (int k = 0; k < 4; ++k) {
                unsigned neg = __ballot_sync(0xffffffffu, e[k] < 0.0f);
                unsigned nz  = __ballot_sync(0xffffffffu, e[k] != 0.0f);
                if (lane == 0) {
                    s_xneg[c * 4 + k][warp] = neg;
                    s_xnz [c * 4 + k][warp] = nz;
                }
            }
        }
    }
    __syncthreads();

    // ---- Phase B: one warp per W row, float4 loads, batch-in-lane popc ----
    {
        const int row = blockIdx.x * ROWS_PER_BLOCK + warp;
        const float4* wr = (const float4*)(Wm + (size_t)row * HID);
        const int batch = lane & 7;   // lanes b, b+8, b+16, b+24 replicate batch b

        int   acc  = 0;
        float asum = 0.0f;

        #pragma unroll
        for (int c = 0; c < CHUNKS; ++c) {
            float4 v = __ldg(wr + c * 32 + lane);
            const float e[4] = {v.x, v.y, v.z, v.w};
            asum += fabsf(e[0]) + fabsf(e[1]) + fabsf(e[2]) + fabsf(e[3]);
            #pragma unroll
            for (int k = 0; k < 4; ++k) {
                unsigned wneg = __ballot_sync(0xffffffffu, e[k] < 0.0f);
                unsigned wnz  = __ballot_sync(0xffffffffu, e[k] != 0.0f);
                unsigned valid = s_xnz[c * 4 + k][batch] & wnz;
                unsigned diff  = (s_xneg[c * 4 + k][batch] ^ wneg) & valid;
                acc += __popc(valid) - 2 * __popc(diff);
            }
        }

        // |W| warp reduce
        #pragma unroll
        for (int off = 16; off > 0; off >>= 1)
            asum += __shfl_xor_sync(0xffffffffu, asum, off);

        if (lane < BATCH) g_dot[row * BATCH + lane] = acc;   // lanes 0-7 exact
        if (lane == 0)    g_wpart[row] = asum;
    }

    // ---- Phase C: last block does the epilogue ----
    __threadfence();
    __syncthreads();

    __shared__ bool s_last;
    if (tid == 0) {
        unsigned t = atomicAdd(&g_ticket, 1u);
        s_last = (t == (unsigned)(gridDim.x - 1));
        if (s_last) g_ticket = 0;          // reset for next graph replay
    }
    __syncthreads();
    if (!s_last) return;
    __threadfence();   // acquire: all blocks' g_dot/g_wpart now visible

    // Reduce sum|W| over 1024 rows with 256 threads
    __shared__ float red[NTHREADS];
    float s = 0.0f;
    #pragma unroll
    for (int k = 0; k < HID / NTHREADS; ++k)
        s += g_wpart[tid + k * NTHREADS];
    red[tid] = s;
    __syncthreads();
    #pragma unroll
    for (int stp = NTHREADS / 2; stp > 0; stp >>= 1) {
        if (tid < stp) red[tid] += red[tid + stp];
        __syncthreads();
    }

    const float wscale = red[0] * (1.0f / ((float)HID * (float)HID));
    const float a      = fmaxf(__ldg(alpha), 1e-5f);
    const float scale  = a * wscale;

    // out[b*HID + o] = tanh(scale * dot[o][b] + bias[o]); idx == b*HID+o
    #pragma unroll
    for (int k = 0; k < (BATCH * HID) / NTHREADS; ++k) {
        int idx = tid + k * NTHREADS;
        int b   = idx >> 10;          // idx / HID
        int o   = idx & (HID - 1);    // idx % HID
        out[idx] = tanhf(scale * (float)g_dot[o * BATCH + b] + __ldg(bias + o));
    }
}

extern "C" void kernel_launch(void* const* d_in, const int* in_sizes, int n_in,
                              void* d_out, int out_size)
{
    const float* x     = (const float*)d_in[0];
    const float* Wm    = (const float*)d_in[1];
    const float* bias  = (const float*)d_in[2];
    const float* alpha = (const float*)d_in[3];
    float* out = (float*)d_out;

    fused_pooler_kernel<<<NBLOCKS, NTHREADS>>>(x, Wm, bias, alpha, out);
}